// round 5
// baseline (speedup 1.0000x reference)
#include <cuda_runtime.h>

// FastRotation — warp-autonomous, pair-tile version (resubmission; R4 bench
// died to a container-acquisition failure, not a kernel fault).
// One warp per 5x5x5 volume. Volume staged into shared as a zero-padded tile
// of float2 PAIRS: entry (z,y,xp) holds (v[z][y][xp-1], v[z][y][xp]), with
// z,y in [-1..5] and xp in [0..5]. Trilinear's two x-adjacent taps then come
// from ONE LDS.64 -> 4 wide loads per point instead of 8 scalar loads.
// Out-of-range lanes (exact zeros) skip the loads entirely.

#define KVOL 125
#define PDY  7              // y,z padded dims: -1..5
#define PDX  6              // x pair slots: 0..5
#define PPAIRS (PDY * PDY * PDX)   // 294
#define PSTR 296            // pairs per volume, padded for float4 zero-fill
#define WPB  8              // warps (= volumes) per block
#define TPB  (WPB * 32)

// Base-lattice coords per point p = i*25 + j*5 + l : c = 0.5*idx - 1
#define BV(v) (0.5f * (v) - 1.0f)
#define E4(i,j,l) {BV(i), BV(j), BV(l), 0.0f}
#define R5(i,j)  E4(i,j,0), E4(i,j,1), E4(i,j,2), E4(i,j,3), E4(i,j,4)
#define P25(i)   R5(i,0), R5(i,1), R5(i,2), R5(i,3), R5(i,4)
__device__ const float4 g_base[128] = { P25(0), P25(1), P25(2), P25(3), P25(4) };

// Scatter word-offsets (in floats) for element m = z*25 + y*5 + x:
//   v[m] is the .x of pair (z,y,x+1) and the .y of pair (z,y,x)
#define PBASE(i,j,xp) ((((i)+1)*PDY + ((j)+1))*PDX + (xp))
#define POFF(i,j,l) { 2*PBASE(i,j,(l)+1), 2*PBASE(i,j,l) + 1 }
#define PO5(i,j)  POFF(i,j,0), POFF(i,j,1), POFF(i,j,2), POFF(i,j,3), POFF(i,j,4)
#define PO25(i)   PO5(i,0), PO5(i,1), PO5(i,2), PO5(i,3), PO5(i,4)
__device__ const int2 g_poff[128] = { PO25(0), PO25(1), PO25(2), PO25(3), PO25(4) };

__global__ __launch_bounds__(TPB) void fast_rotation_kernel(
    const float* __restrict__ vol,      // [N,125]
    const float* __restrict__ theta_v,  // [N,3]
    const float* __restrict__ theta,    // [N]
    float* __restrict__ out,            // [N,125]
    int N)
{
    __shared__ float2 sp[WPB * PSTR];

    const int w    = threadIdx.x >> 5;
    const int lane = threadIdx.x & 31;
    const int n    = blockIdx.x * WPB + w;
    if (n >= N) return;

    float2* ptile = &sp[w * PSTR];
    float*  tilef = (float*)ptile;

    // Zero-fill: 296 pairs = 592 floats = 148 float4 per volume
    {
        float4* t4 = (float4*)ptile;
        const float4 z4 = make_float4(0.f, 0.f, 0.f, 0.f);
        t4[lane]      = z4;
        t4[lane + 32] = z4;
        t4[lane + 64] = z4;
        t4[lane + 96] = z4;
        if (lane < 148 - 128) t4[lane + 128] = z4;
    }
    __syncwarp();

    // Scatter volume into pair tile: each element lands in two float words
    // (distinct words; no races). Coalesced global reads.
    const float* vsrc = vol + n * KVOL;
    #pragma unroll
    for (int q = 0; q < 4; ++q) {
        const int m = lane + 32 * q;
        if (m < KVOL) {
            const float v = __ldcs(vsrc + m);
            const int2 o = g_poff[m];
            tilef[o.x] = v;
            tilef[o.y] = v;
        }
    }

    // Rodrigues matrix, redundantly per lane (broadcast loads), pre-scaled by
    // 2 so pixel coord = base . (2R) + 2.
    const float tx = theta_v[n * 3 + 0];
    const float ty = theta_v[n * 3 + 1];
    const float tz = theta_v[n * 3 + 2];
    const float inv = rsqrtf(fmaxf(tx * tx + ty * ty + tz * tz, 1e-24f));
    const float vx = tx * inv, vy = ty * inv, vz = tz * inv;
    const float a  = theta[n];
    const float ss = 2.0f * __sinf(a);
    const float cs = 2.0f * (1.0f - __cosf(a));
    const float vv = vx * vx + vy * vy + vz * vz;   // ~1; keep exact form
    const float R00 = 2.0f + cs * (vx * vx - vv);
    const float R01 = -ss * vz + cs * (vx * vy);
    const float R02 =  ss * vy + cs * (vx * vz);
    const float R10 =  ss * vz + cs * (vy * vx);
    const float R11 = 2.0f + cs * (vy * vy - vv);
    const float R12 = -ss * vx + cs * (vy * vz);
    const float R20 = -ss * vy + cs * (vz * vx);
    const float R21 =  ss * vx + cs * (vz * vy);
    const float R22 = 2.0f + cs * (vz * vz - vv);

    __syncwarp();   // pair tile visible warp-wide

    float* dst = out + n * KVOL;

    #pragma unroll
    for (int q = 0; q < 4; ++q) {
        const int p = lane + 32 * q;
        if (p < KVOL) {
            const float4 b = g_base[p];
            const float x = fmaf(b.x, R00, fmaf(b.y, R10, fmaf(b.z, R20, 2.0f)));
            const float y = fmaf(b.x, R01, fmaf(b.y, R11, fmaf(b.z, R21, 2.0f)));
            const float z = fmaf(b.x, R02, fmaf(b.y, R12, fmaf(b.z, R22, 2.0f)));

            const int x0 = __float2int_rd(x);
            const int y0 = __float2int_rd(y);
            const int z0 = __float2int_rd(z);
            const float wx = x - (float)x0;
            const float wy = y - (float)y0;
            const float wz = z - (float)z0;

            // In-range iff base cell in [-1,4] per axis; else exact zero.
            const int xp = x0 + 1, yp = y0 + 1, zp = z0 + 1;
            const bool ok = ((unsigned)xp <= 5u) &
                            ((unsigned)yp <= 5u) &
                            ((unsigned)zp <= 5u);

            float r = 0.0f;
            if (ok) {
                const float2* pb = ptile + (zp * PDY + yp) * PDX + xp;
                const float2 a00 = pb[0];
                const float2 a10 = pb[PDX];
                const float2 a01 = pb[PDY * PDX];
                const float2 a11 = pb[PDY * PDX + PDX];

                const float wx0 = 1.0f - wx;
                const float h00 = fmaf(wx, a00.y, wx0 * a00.x);
                const float h10 = fmaf(wx, a10.y, wx0 * a10.x);
                const float h01 = fmaf(wx, a01.y, wx0 * a01.x);
                const float h11 = fmaf(wx, a11.y, wx0 * a11.x);

                const float lo = fmaf(wy, h10, (1.0f - wy) * h00);
                const float hi = fmaf(wy, h11, (1.0f - wy) * h01);
                r = fmaf(wz, hi, (1.0f - wz) * lo);
            }
            dst[p] = r;
        }
    }
}

extern "C" void kernel_launch(void* const* d_in, const int* in_sizes, int n_in,
                              void* d_out, int out_size)
{
    const float* vol     = (const float*)d_in[0];  // input_filter [N,5,5,5]
    const float* theta_v = (const float*)d_in[1];  // [N,3]
    const float* theta   = (const float*)d_in[2];  // [N]
    float* out = (float*)d_out;

    const int N = in_sizes[2];                     // theta has N elements
    const int blocks = (N + WPB - 1) / WPB;
    fast_rotation_kernel<<<blocks, TPB>>>(vol, theta_v, theta, out, N);
}

// round 6
// speedup vs baseline: 1.4890x; 1.4890x over previous
#include <cuda_runtime.h>
#include <cuda_fp16.h>

// FastRotation — warp-autonomous, half2 pair-tile version.
// One warp per 5x5x5 volume. Volume stored in shared as zero-padded half2
// PAIRS: slot (z,y,xp) holds (v[z][y][xp-1], v[z][y][xp]) packed in 4 bytes,
// z,y in [-1..5], xp in [0..5]. Trilinear's two x-adjacent taps come from one
// 32-bit LDS (single bank per lane) -> 4 LDS.32 per point, HALF the loads and
// HALF the smem bytes of the scalar version with the same conflict profile.
// Weights/accumulation stay fp32; only the volume is fp16-quantized.

#define KVOL 125
#define PDY  7              // y,z padded dims: -1..5
#define PDX  6              // x pair slots: 0..5
#define PPAIRS (PDY * PDY * PDX)   // 294 half2
#define PSTR 296            // half2 per volume, padded to float4 multiple
#define WPB  8              // warps (= volumes) per block
#define TPB  (WPB * 32)

// Base-lattice coords per point p = i*25 + j*5 + l : c = 0.5*idx - 1
#define BV(v) (0.5f * (v) - 1.0f)
#define E4(i,j,l) {BV(i), BV(j), BV(l), 0.0f}
#define R5(i,j)  E4(i,j,0), E4(i,j,1), E4(i,j,2), E4(i,j,3), E4(i,j,4)
#define P25(i)   R5(i,0), R5(i,1), R5(i,2), R5(i,3), R5(i,4)
__device__ const float4 g_base[128] = { P25(0), P25(1), P25(2), P25(3), P25(4) };

// Scatter half-word offsets for element m = z*25 + y*5 + x:
//   v[m] is the HI half (.y) of slot (z,y,x) and the LO half (.x) of slot (z,y,x+1)
#define PBASE(i,j,xp) ((((i)+1)*PDY + ((j)+1))*PDX + (xp))
#define POFF(i,j,l) { 2*PBASE(i,j,(l)+1), 2*PBASE(i,j,l) + 1 }
#define PO5(i,j)  POFF(i,j,0), POFF(i,j,1), POFF(i,j,2), POFF(i,j,3), POFF(i,j,4)
#define PO25(i)   PO5(i,0), PO5(i,1), PO5(i,2), PO5(i,3), PO5(i,4)
__device__ const int2 g_poff[128] = { PO25(0), PO25(1), PO25(2), PO25(3), PO25(4) };

__global__ __launch_bounds__(TPB) void fast_rotation_kernel(
    const float* __restrict__ vol,      // [N,125]
    const float* __restrict__ theta_v,  // [N,3]
    const float* __restrict__ theta,    // [N]
    float* __restrict__ out,            // [N,125]
    int N)
{
    __shared__ __half2 sp[WPB * PSTR];

    const int w    = threadIdx.x >> 5;
    const int lane = threadIdx.x & 31;
    const int n    = blockIdx.x * WPB + w;
    if (n >= N) return;

    __half2* ptile = &sp[w * PSTR];
    __half*  tileh = (__half*)ptile;

    // Zero-fill: 296 half2 = 1184 B = 74 float4 per volume
    {
        float4* t4 = (float4*)ptile;
        const float4 z4 = make_float4(0.f, 0.f, 0.f, 0.f);
        t4[lane]      = z4;
        t4[lane + 32] = z4;
        if (lane < 74 - 64) t4[lane + 64] = z4;
    }
    __syncwarp();

    // Scatter volume into pair tile (fp16). Each element lands in two
    // distinct half-words; no races. Coalesced global reads.
    const float* vsrc = vol + n * KVOL;
    #pragma unroll
    for (int q = 0; q < 4; ++q) {
        const int m = lane + 32 * q;
        if (m < KVOL) {
            const __half h = __float2half_rn(__ldcs(vsrc + m));
            const int2 o = g_poff[m];
            tileh[o.x] = h;
            tileh[o.y] = h;
        }
    }

    // Rodrigues matrix, redundantly per lane (broadcast loads), pre-scaled by
    // 2 so pixel coord = base . (2R) + 2.
    const float tx = theta_v[n * 3 + 0];
    const float ty = theta_v[n * 3 + 1];
    const float tz = theta_v[n * 3 + 2];
    const float inv = rsqrtf(fmaxf(tx * tx + ty * ty + tz * tz, 1e-24f));
    const float vx = tx * inv, vy = ty * inv, vz = tz * inv;
    const float a  = theta[n];
    const float ss = 2.0f * __sinf(a);
    const float cs = 2.0f * (1.0f - __cosf(a));
    const float vv = vx * vx + vy * vy + vz * vz;   // ~1; keep exact form
    const float R00 = 2.0f + cs * (vx * vx - vv);
    const float R01 = -ss * vz + cs * (vx * vy);
    const float R02 =  ss * vy + cs * (vx * vz);
    const float R10 =  ss * vz + cs * (vy * vx);
    const float R11 = 2.0f + cs * (vy * vy - vv);
    const float R12 = -ss * vx + cs * (vy * vz);
    const float R20 = -ss * vy + cs * (vz * vx);
    const float R21 =  ss * vx + cs * (vz * vy);
    const float R22 = 2.0f + cs * (vz * vz - vv);

    __syncwarp();   // pair tile visible warp-wide

    float* dst = out + n * KVOL;

    #pragma unroll
    for (int q = 0; q < 4; ++q) {
        const int p = lane + 32 * q;
        if (p < KVOL) {
            const float4 b = g_base[p];
            const float x = fmaf(b.x, R00, fmaf(b.y, R10, fmaf(b.z, R20, 2.0f)));
            const float y = fmaf(b.x, R01, fmaf(b.y, R11, fmaf(b.z, R21, 2.0f)));
            const float z = fmaf(b.x, R02, fmaf(b.y, R12, fmaf(b.z, R22, 2.0f)));

            const int x0 = __float2int_rd(x);
            const int y0 = __float2int_rd(y);
            const int z0 = __float2int_rd(z);
            const float wx = x - (float)x0;
            const float wy = y - (float)y0;
            const float wz = z - (float)z0;

            // In-range iff base cell in [-1,4] per axis; else exact zero.
            const int xp = x0 + 1, yp = y0 + 1, zp = z0 + 1;
            const bool ok = ((unsigned)xp <= 5u) &
                            ((unsigned)yp <= 5u) &
                            ((unsigned)zp <= 5u);

            float r = 0.0f;
            if (ok) {
                // Slot xp = x0+1 holds (v[x0], v[x0+1]).
                const __half2* pb = ptile + (zp * PDY + yp) * PDX + xp;
                const float2 f00 = __half22float2(pb[0]);                 // (z0 ,y0 )
                const float2 f10 = __half22float2(pb[PDX]);               // (z0 ,y0+1)
                const float2 f01 = __half22float2(pb[PDY * PDX]);         // (z0+1,y0 )
                const float2 f11 = __half22float2(pb[PDY * PDX + PDX]);   // (z0+1,y0+1)

                const float wx0 = 1.0f - wx;
                const float h00 = fmaf(wx, f00.y, wx0 * f00.x);
                const float h10 = fmaf(wx, f10.y, wx0 * f10.x);
                const float h01 = fmaf(wx, f01.y, wx0 * f01.x);
                const float h11 = fmaf(wx, f11.y, wx0 * f11.x);

                const float lo = fmaf(wy, h10, (1.0f - wy) * h00);
                const float hi = fmaf(wy, h11, (1.0f - wy) * h01);
                r = fmaf(wz, hi, (1.0f - wz) * lo);
            }
            dst[p] = r;
        }
    }
}

extern "C" void kernel_launch(void* const* d_in, const int* in_sizes, int n_in,
                              void* d_out, int out_size)
{
    const float* vol     = (const float*)d_in[0];  // input_filter [N,5,5,5]
    const float* theta_v = (const float*)d_in[1];  // [N,3]
    const float* theta   = (const float*)d_in[2];  // [N]
    float* out = (float*)d_out;

    const int N = in_sizes[2];                     // theta has N elements
    const int blocks = (N + WPB - 1) / WPB;
    fast_rotation_kernel<<<blocks, TPB>>>(vol, theta_v, theta, out, N);
}

// round 8
// speedup vs baseline: 1.5549x; 1.0443x over previous
#include <cuda_runtime.h>
#include <cuda_fp16.h>

// FastRotation — warp-autonomous half2 pair tile, v2.
// (Resubmission: R7 bench died on container acquisition, not kernel fault.)
// vs R6: (a) index tables replaced by mul-shift arithmetic (kills ~24 L1
// wavefronts/warp of table LDG), (b) y/z lerps in packed fp16 HFMA2 with a
// single half2->float2 convert (−10 instrs/point), (c) odd bank strides
// (row=7 words, slab=49) to reduce LDS conflict degree.
// Tile: slot (z,y,xp) at word ((z+1)*7+(y+1))*7 + xp holds the fp16 x-pair
// (v[z][y][xp-1], v[z][y][xp]); z,y in [-1..5], xp in [0..5]; borders zero.

#define KVOL  125
#define ZSTR  49          // words per z-slab (7 rows * 7 words)
#define YSTR  7           // words per row (odd)
#define WORDS 344         // 343 padded to float4 multiple
#define WPB   8           // warps (= volumes) per block
#define TPB   (WPB * 32)

__global__ __launch_bounds__(TPB) void fast_rotation_kernel(
    const float* __restrict__ vol,      // [N,125]
    const float* __restrict__ theta_v,  // [N,3]
    const float* __restrict__ theta,    // [N]
    float* __restrict__ out,            // [N,125]
    int N)
{
    __shared__ __half2 sp[WPB * WORDS];

    const int w    = threadIdx.x >> 5;
    const int lane = threadIdx.x & 31;
    const int n    = blockIdx.x * WPB + w;
    if (n >= N) return;

    __half2* tile  = &sp[w * WORDS];
    __half*  tileh = (__half*)tile;

    // Zero-fill: 344 half2 = 1376 B = 86 float4
    {
        float4* t4 = (float4*)tile;
        const float4 z4 = make_float4(0.f, 0.f, 0.f, 0.f);
        t4[lane]      = z4;
        t4[lane + 32] = z4;
        if (lane < 86 - 64) t4[lane + 64] = z4;
    }
    __syncwarp();

    // Scatter volume into pair tile (fp16). Element m = z*25+y*5+x lands as
    // .y of slot (z,y,x) and .x of slot (z,y,x+1): half indices 2b+1, 2b+2
    // with b = ((z+1)*7+(y+1))*7 + x. Distinct half-words; no races.
    const float* vsrc = vol + n * KVOL;
    #pragma unroll
    for (int q = 0; q < 4; ++q) {
        const int m = lane + 32 * q;
        if (m < KVOL) {
            const __half h = __float2half_rn(__ldcs(vsrc + m));
            const int z   = (m * 41) >> 10;       // m / 25   (m < 128)
            const int rem = m - 25 * z;
            const int y   = (rem * 205) >> 10;    // rem / 5  (rem < 32)
            const int x   = rem - 5 * y;
            const int b   = ((z + 1) * 7 + (y + 1)) * YSTR + x;
            tileh[2 * b + 1] = h;
            tileh[2 * b + 2] = h;
        }
    }

    // Rodrigues matrix, redundantly per lane (broadcast loads), pre-scaled by
    // 2 so pixel coord = base . (2R) + 2.
    const float tx = theta_v[n * 3 + 0];
    const float ty = theta_v[n * 3 + 1];
    const float tz = theta_v[n * 3 + 2];
    const float inv = rsqrtf(fmaxf(tx * tx + ty * ty + tz * tz, 1e-24f));
    const float vx = tx * inv, vy = ty * inv, vz = tz * inv;
    const float a  = theta[n];
    const float ss = 2.0f * __sinf(a);
    const float cs = 2.0f * (1.0f - __cosf(a));
    const float vv = vx * vx + vy * vy + vz * vz;   // ~1; keep exact form
    const float R00 = 2.0f + cs * (vx * vx - vv);
    const float R01 = -ss * vz + cs * (vx * vy);
    const float R02 =  ss * vy + cs * (vx * vz);
    const float R10 =  ss * vz + cs * (vy * vx);
    const float R11 = 2.0f + cs * (vy * vy - vv);
    const float R12 = -ss * vx + cs * (vy * vz);
    const float R20 = -ss * vy + cs * (vz * vx);
    const float R21 =  ss * vx + cs * (vz * vy);
    const float R22 = 2.0f + cs * (vz * vz - vv);

    __syncwarp();   // tile visible warp-wide

    const __half2 one2 = __float2half2_rn(1.0f);
    float* dst = out + n * KVOL;

    #pragma unroll
    for (int q = 0; q < 4; ++q) {
        const int p = lane + 32 * q;
        if (p < KVOL) {
            // p -> (i,j,l) via mul-shift division (no tables)
            const int i   = (p * 41) >> 10;
            const int rem = p - 25 * i;
            const int j   = (rem * 205) >> 10;
            const int l   = rem - 5 * j;
            const float bi = fmaf((float)i, 0.5f, -1.0f);
            const float bj = fmaf((float)j, 0.5f, -1.0f);
            const float bl = fmaf((float)l, 0.5f, -1.0f);

            // pixel coords: (grid + 1) * 2 = base . (2R) + 2
            const float x = fmaf(bi, R00, fmaf(bj, R10, fmaf(bl, R20, 2.0f)));
            const float y = fmaf(bi, R01, fmaf(bj, R11, fmaf(bl, R21, 2.0f)));
            const float z = fmaf(bi, R02, fmaf(bj, R12, fmaf(bl, R22, 2.0f)));

            const int x0 = __float2int_rd(x);
            const int y0 = __float2int_rd(y);
            const int z0 = __float2int_rd(z);
            const float wx = x - (float)x0;
            const float wy = y - (float)y0;
            const float wz = z - (float)z0;

            // In-range iff base cell in [-1,4] per axis; else exact zero.
            const bool ok = ((unsigned)(x0 + 1) <= 5u) &
                            ((unsigned)(y0 + 1) <= 5u) &
                            ((unsigned)(z0 + 1) <= 5u);

            float r = 0.0f;
            if (ok) {
                // slot (z0,y0,x0+1): word = (z0+1)*49 + (y0+1)*7 + x0+1
                const int wd = z0 * ZSTR + y0 * YSTR + x0 + (ZSTR + YSTR + 1);
                const __half2 f00 = tile[wd];              // (z0 , y0 ) x-pair
                const __half2 f10 = tile[wd + YSTR];       // (z0 , y0+1)
                const __half2 f01 = tile[wd + ZSTR];       // (z0+1, y0 )
                const __half2 f11 = tile[wd + ZSTR + YSTR];// (z0+1, y0+1)

                const __half2 wyb  = __float2half2_rn(wy);
                const __half2 wy0b = __hsub2(one2, wyb);
                const __half2 wzb  = __float2half2_rn(wz);
                const __half2 wz0b = __hsub2(one2, wzb);

                const __half2 a0 = __hfma2(f10, wyb, __hmul2(f00, wy0b));
                const __half2 a1 = __hfma2(f11, wyb, __hmul2(f01, wy0b));
                const __half2 g  = __hfma2(a1, wzb, __hmul2(a0, wz0b));

                const float2 gf = __half22float2(g);
                r = fmaf(wx, gf.y, (1.0f - wx) * gf.x);
            }
            dst[p] = r;
        }
    }
}

extern "C" void kernel_launch(void* const* d_in, const int* in_sizes, int n_in,
                              void* d_out, int out_size)
{
    const float* vol     = (const float*)d_in[0];  // input_filter [N,5,5,5]
    const float* theta_v = (const float*)d_in[1];  // [N,3]
    const float* theta   = (const float*)d_in[2];  // [N]
    float* out = (float*)d_out;

    const int N = in_sizes[2];                     // theta has N elements
    const int blocks = (N + WPB - 1) / WPB;
    fast_rotation_kernel<<<blocks, TPB>>>(vol, theta_v, theta, out, N);
}

// round 9
// speedup vs baseline: 1.6129x; 1.0373x over previous
#include <cuda_runtime.h>
#include <cuda_fp16.h>

// FastRotation — warp-autonomous half2 pair tile, v3.
// vs R8 (now issue-bound: issue 90%, L1 70%): move per-point lattice coords
// and scatter offsets back into small L1-resident tables (LDG) instead of
// mul-shift ALU — trades ~12 issue slots/point for 1 LDG.128 against L1
// headroom. Memory structure (fp16 pair tile, odd strides 7/49, packed
// HFMA2 lerp) unchanged from R8.

#define KVOL  125
#define ZSTR  49          // words per z-slab (7 rows * 7 words)
#define YSTR  7           // words per row (odd)
#define WORDS 344         // 343 padded to float4 multiple
#define WPB   8           // warps (= volumes) per block
#define TPB   (WPB * 32)

// Base-lattice coords per point p = i*25 + j*5 + l : c = 0.5*idx - 1
#define BV(v) (0.5f * (v) - 1.0f)
#define E4(i,j,l) {BV(i), BV(j), BV(l), 0.0f}
#define R5(i,j)  E4(i,j,0), E4(i,j,1), E4(i,j,2), E4(i,j,3), E4(i,j,4)
#define P25(i)   R5(i,0), R5(i,1), R5(i,2), R5(i,3), R5(i,4)
__device__ const float4 g_base[128] = { P25(0), P25(1), P25(2), P25(3), P25(4) };

// Pair-tile slot index for element m = z*25 + y*5 + x:
//   b = ((z+1)*7 + (y+1))*7 + x ; element is half 2b+1 and 2b+2
#define PB(i,j,l) (((i + 1) * 7 + (j + 1)) * YSTR + (l))
#define B5(i,j)  PB(i,j,0), PB(i,j,1), PB(i,j,2), PB(i,j,3), PB(i,j,4)
#define B25(i)   B5(i,0), B5(i,1), B5(i,2), B5(i,3), B5(i,4)
__device__ const int g_b[128] = { B25(0), B25(1), B25(2), B25(3), B25(4) };

__global__ __launch_bounds__(TPB) void fast_rotation_kernel(
    const float* __restrict__ vol,      // [N,125]
    const float* __restrict__ theta_v,  // [N,3]
    const float* __restrict__ theta,    // [N]
    float* __restrict__ out,            // [N,125]
    int N)
{
    __shared__ __half2 sp[WPB * WORDS];

    const int w    = threadIdx.x >> 5;
    const int lane = threadIdx.x & 31;
    const int n    = blockIdx.x * WPB + w;
    if (n >= N) return;

    __half2* tile  = &sp[w * WORDS];
    __half*  tileh = (__half*)tile;

    // Zero-fill: 344 half2 = 1376 B = 86 float4
    {
        float4* t4 = (float4*)tile;
        const float4 z4 = make_float4(0.f, 0.f, 0.f, 0.f);
        t4[lane]      = z4;
        t4[lane + 32] = z4;
        if (lane < 86 - 64) t4[lane + 64] = z4;
    }
    __syncwarp();

    // Scatter volume into pair tile (fp16): element m -> halves 2b+1, 2b+2,
    // slot index b from table. Distinct half-words; no races.
    const float* vsrc = vol + n * KVOL;
    #pragma unroll
    for (int q = 0; q < 4; ++q) {
        const int m = lane + 32 * q;
        if (m < KVOL) {
            const __half h = __float2half_rn(__ldcs(vsrc + m));
            const int b = __ldg(&g_b[m]);
            tileh[2 * b + 1] = h;
            tileh[2 * b + 2] = h;
        }
    }

    // Rodrigues matrix, redundantly per lane (broadcast loads), pre-scaled by
    // 2 so pixel coord = base . (2R) + 2.
    const float tx = theta_v[n * 3 + 0];
    const float ty = theta_v[n * 3 + 1];
    const float tz = theta_v[n * 3 + 2];
    const float inv = rsqrtf(fmaxf(tx * tx + ty * ty + tz * tz, 1e-24f));
    const float vx = tx * inv, vy = ty * inv, vz = tz * inv;
    const float a  = theta[n];
    const float ss = 2.0f * __sinf(a);
    const float cs = 2.0f * (1.0f - __cosf(a));
    const float vv = vx * vx + vy * vy + vz * vz;   // ~1; keep exact form
    const float R00 = 2.0f + cs * (vx * vx - vv);
    const float R01 = -ss * vz + cs * (vx * vy);
    const float R02 =  ss * vy + cs * (vx * vz);
    const float R10 =  ss * vz + cs * (vy * vx);
    const float R11 = 2.0f + cs * (vy * vy - vv);
    const float R12 = -ss * vx + cs * (vy * vz);
    const float R20 = -ss * vy + cs * (vz * vx);
    const float R21 =  ss * vx + cs * (vz * vy);
    const float R22 = 2.0f + cs * (vz * vz - vv);

    __syncwarp();   // tile visible warp-wide

    const __half2 one2 = __float2half2_rn(1.0f);
    float* dst = out + n * KVOL;

    #pragma unroll
    for (int q = 0; q < 4; ++q) {
        const int p = lane + 32 * q;
        if (p < KVOL) {
            const float4 b = __ldg(&g_base[p]);

            // pixel coords: (grid + 1) * 2 = base . (2R) + 2
            const float x = fmaf(b.x, R00, fmaf(b.y, R10, fmaf(b.z, R20, 2.0f)));
            const float y = fmaf(b.x, R01, fmaf(b.y, R11, fmaf(b.z, R21, 2.0f)));
            const float z = fmaf(b.x, R02, fmaf(b.y, R12, fmaf(b.z, R22, 2.0f)));

            const int x0 = __float2int_rd(x);
            const int y0 = __float2int_rd(y);
            const int z0 = __float2int_rd(z);
            const float wx = x - (float)x0;
            const float wy = y - (float)y0;
            const float wz = z - (float)z0;

            // In-range iff base cell in [-1,4] per axis; else exact zero.
            const bool ok = ((unsigned)(x0 + 1) <= 5u) &
                            ((unsigned)(y0 + 1) <= 5u) &
                            ((unsigned)(z0 + 1) <= 5u);

            float r = 0.0f;
            if (ok) {
                // slot (z0,y0,x0+1): word = (z0+1)*49 + (y0+1)*7 + x0+1
                const int wd = z0 * ZSTR + y0 * YSTR + x0 + (ZSTR + YSTR + 1);
                const __half2 f00 = tile[wd];              // (z0 , y0 ) x-pair
                const __half2 f10 = tile[wd + YSTR];       // (z0 , y0+1)
                const __half2 f01 = tile[wd + ZSTR];       // (z0+1, y0 )
                const __half2 f11 = tile[wd + ZSTR + YSTR];// (z0+1, y0+1)

                const __half2 wyb  = __float2half2_rn(wy);
                const __half2 wy0b = __hsub2(one2, wyb);
                const __half2 wzb  = __float2half2_rn(wz);
                const __half2 wz0b = __hsub2(one2, wzb);

                const __half2 a0 = __hfma2(f10, wyb, __hmul2(f00, wy0b));
                const __half2 a1 = __hfma2(f11, wyb, __hmul2(f01, wy0b));
                const __half2 g  = __hfma2(a1, wzb, __hmul2(a0, wz0b));

                const float2 gf = __half22float2(g);
                r = fmaf(wx, gf.y, (1.0f - wx) * gf.x);
            }
            dst[p] = r;
        }
    }
}

extern "C" void kernel_launch(void* const* d_in, const int* in_sizes, int n_in,
                              void* d_out, int out_size)
{
    const float* vol     = (const float*)d_in[0];  // input_filter [N,5,5,5]
    const float* theta_v = (const float*)d_in[1];  // [N,3]
    const float* theta   = (const float*)d_in[2];  // [N]
    float* out = (float*)d_out;

    const int N = in_sizes[2];                     // theta has N elements
    const int blocks = (N + WPB - 1) / WPB;
    fast_rotation_kernel<<<blocks, TPB>>>(vol, theta_v, theta, out, N);
}

// round 10
// speedup vs baseline: 1.7181x; 1.0652x over previous
#include <cuda_runtime.h>
#include <cuda_fp16.h>

// FastRotation — warp-autonomous half2 pair tile, v4.
// vs R9 (L1-roofed at 94.8%): (a) base-coord table packed as fp16 in uint2
// (LDG.64, halves its L1 wavefronts 16->8; coords {0,±0.5,±1} are fp16-exact),
// (b) lerps rewritten a + w*(b-a) (no complement terms, -3 instr/point),
// (c) vv==1 in Rodrigues (v is normalized).
// Tile: slot (z,y,xp) at word ((z+1)*7+(y+1))*7+xp holds fp16 x-pair
// (v[z][y][xp-1], v[z][y][xp]); z,y in [-1..5], xp in [0..5]; borders zero.

#define KVOL  125
#define ZSTR  49          // words per z-slab (7 rows * 7 words)
#define YSTR  7           // words per row (odd)
#define WORDS 344         // 343 padded to float4 multiple
#define WPB   8           // warps (= volumes) per block
#define TPB   (WPB * 32)

// fp16 bit patterns for lattice coord c = 0.5*idx - 1, idx in 0..4
#define HP(i) ((i)==0 ? 0xBC00u : (i)==1 ? 0xB800u : (i)==2 ? 0x0000u : \
               (i)==3 ? 0x3800u : 0x3C00u)
// Packed base for point p = i*25 + j*5 + l : u.x = half(bi) | half(bj)<<16, u.y = half(bl)
#define UV(i,j,l) { HP(i) | (HP(j) << 16), HP(l) }
#define U5(i,j)  UV(i,j,0), UV(i,j,1), UV(i,j,2), UV(i,j,3), UV(i,j,4)
#define U25(i)   U5(i,0), U5(i,1), U5(i,2), U5(i,3), U5(i,4)
__device__ const uint2 g_bh[128] = { U25(0), U25(1), U25(2), U25(3), U25(4) };

// Pair-tile slot index for element m = z*25 + y*5 + x:
//   b = ((z+1)*7 + (y+1))*7 + x ; element is half 2b+1 and 2b+2
#define PB(i,j,l) (((i + 1) * 7 + (j + 1)) * YSTR + (l))
#define B5(i,j)  PB(i,j,0), PB(i,j,1), PB(i,j,2), PB(i,j,3), PB(i,j,4)
#define B25(i)   B5(i,0), B5(i,1), B5(i,2), B5(i,3), B5(i,4)
__device__ const int g_b[128] = { B25(0), B25(1), B25(2), B25(3), B25(4) };

__global__ __launch_bounds__(TPB) void fast_rotation_kernel(
    const float* __restrict__ vol,      // [N,125]
    const float* __restrict__ theta_v,  // [N,3]
    const float* __restrict__ theta,    // [N]
    float* __restrict__ out,            // [N,125]
    int N)
{
    __shared__ __half2 sp[WPB * WORDS];

    const int w    = threadIdx.x >> 5;
    const int lane = threadIdx.x & 31;
    const int n    = blockIdx.x * WPB + w;
    if (n >= N) return;

    __half2* tile  = &sp[w * WORDS];
    __half*  tileh = (__half*)tile;

    // Zero-fill: 344 half2 = 1376 B = 86 float4
    {
        float4* t4 = (float4*)tile;
        const float4 z4 = make_float4(0.f, 0.f, 0.f, 0.f);
        t4[lane]      = z4;
        t4[lane + 32] = z4;
        if (lane < 86 - 64) t4[lane + 64] = z4;
    }
    __syncwarp();

    // Scatter volume into pair tile (fp16): element m -> halves 2b+1, 2b+2.
    const float* vsrc = vol + n * KVOL;
    #pragma unroll
    for (int q = 0; q < 4; ++q) {
        const int m = lane + 32 * q;
        if (m < KVOL) {
            const __half h = __float2half_rn(__ldcs(vsrc + m));
            const int b = __ldg(&g_b[m]);
            tileh[2 * b + 1] = h;
            tileh[2 * b + 2] = h;
        }
    }

    // Rodrigues matrix, redundantly per lane (broadcast loads), pre-scaled by
    // 2 so pixel coord = base . (2R) + 2. v is unit, so |v|^2 == 1.
    const float tx = theta_v[n * 3 + 0];
    const float ty = theta_v[n * 3 + 1];
    const float tz = theta_v[n * 3 + 2];
    const float inv = rsqrtf(fmaxf(tx * tx + ty * ty + tz * tz, 1e-24f));
    const float vx = tx * inv, vy = ty * inv, vz = tz * inv;
    const float a  = theta[n];
    const float ss = 2.0f * __sinf(a);
    const float cs = 2.0f * (1.0f - __cosf(a));
    const float R00 = 2.0f + cs * (vx * vx - 1.0f);
    const float R01 = -ss * vz + cs * (vx * vy);
    const float R02 =  ss * vy + cs * (vx * vz);
    const float R10 =  ss * vz + cs * (vy * vx);
    const float R11 = 2.0f + cs * (vy * vy - 1.0f);
    const float R12 = -ss * vx + cs * (vy * vz);
    const float R20 = -ss * vy + cs * (vz * vx);
    const float R21 =  ss * vx + cs * (vz * vy);
    const float R22 = 2.0f + cs * (vz * vz - 1.0f);

    __syncwarp();   // tile visible warp-wide

    float* dst = out + n * KVOL;

    #pragma unroll
    for (int q = 0; q < 4; ++q) {
        const int p = lane + 32 * q;
        if (p < KVOL) {
            const uint2 u = __ldg(&g_bh[p]);
            const __half2 hij = *reinterpret_cast<const __half2*>(&u.x);
            const float2 bij  = __half22float2(hij);
            const float  bl   = __half2float(*reinterpret_cast<const __half*>(&u.y));

            // pixel coords: (grid + 1) * 2 = base . (2R) + 2
            const float x = fmaf(bij.x, R00, fmaf(bij.y, R10, fmaf(bl, R20, 2.0f)));
            const float y = fmaf(bij.x, R01, fmaf(bij.y, R11, fmaf(bl, R21, 2.0f)));
            const float z = fmaf(bij.x, R02, fmaf(bij.y, R12, fmaf(bl, R22, 2.0f)));

            const int x0 = __float2int_rd(x);
            const int y0 = __float2int_rd(y);
            const int z0 = __float2int_rd(z);
            const float wx = x - (float)x0;
            const float wy = y - (float)y0;
            const float wz = z - (float)z0;

            // In-range iff base cell in [-1,4] per axis; else exact zero.
            const bool ok = ((unsigned)(x0 + 1) <= 5u) &
                            ((unsigned)(y0 + 1) <= 5u) &
                            ((unsigned)(z0 + 1) <= 5u);

            float r = 0.0f;
            if (ok) {
                // slot (z0,y0,x0+1): word = (z0+1)*49 + (y0+1)*7 + x0+1
                const int wd = z0 * ZSTR + y0 * YSTR + x0 + (ZSTR + YSTR + 1);
                const __half2 f00 = tile[wd];              // (z0 , y0 ) x-pair
                const __half2 f10 = tile[wd + YSTR];       // (z0 , y0+1)
                const __half2 f01 = tile[wd + ZSTR];       // (z0+1, y0 )
                const __half2 f11 = tile[wd + ZSTR + YSTR];// (z0+1, y0+1)

                const __half2 wyb = __float2half2_rn(wy);
                const __half2 wzb = __float2half2_rn(wz);

                // lerp form a + w*(b-a): no complement terms
                const __half2 a0 = __hfma2(__hsub2(f10, f00), wyb, f00);
                const __half2 a1 = __hfma2(__hsub2(f11, f01), wyb, f01);
                const __half2 g  = __hfma2(__hsub2(a1, a0), wzb, a0);

                const float2 gf = __half22float2(g);
                r = fmaf(wx, gf.y - gf.x, gf.x);
            }
            dst[p] = r;
        }
    }
}

extern "C" void kernel_launch(void* const* d_in, const int* in_sizes, int n_in,
                              void* d_out, int out_size)
{
    const float* vol     = (const float*)d_in[0];  // input_filter [N,5,5,5]
    const float* theta_v = (const float*)d_in[1];  // [N,3]
    const float* theta   = (const float*)d_in[2];  // [N]
    float* out = (float*)d_out;

    const int N = in_sizes[2];                     // theta has N elements
    const int blocks = (N + WPB - 1) / WPB;
    fast_rotation_kernel<<<blocks, TPB>>>(vol, theta_v, theta, out, N);
}